// round 11
// baseline (speedup 1.0000x reference)
#include <cuda_runtime.h>
#include <math_constants.h>
#include <cstdint>

#define NA    36864      // 64*64*9 proposals
#define TOPK  6000
#define POST  2000
#define WORDS 94         // ceil(6000/64)
#define WPAD  96
#define NSW   24         // superwords of 256 candidates
#define NCAP  8192       // compacted capacity (power of two)
#define NBINS 1024

typedef unsigned long long ull;

// ---------------- static device scratch (no allocations allowed) ----------------
__device__ float4   g_props[NA];
__device__ unsigned g_skey[NA];
__device__ unsigned g_hist[NBINS + 1];      // [NBINS] = compact counter
__device__ int      g_B;
__device__ ull      g_k64in[NCAP], g_k64out[NCAP];
__device__ float4   g_box[TOPK];
__device__ float    g_bar[TOPK], g_bsc[TOPK];
__device__ ull      g_validm[96];
__device__ ull      g_mask[(size_t)TOPK * WORDS];
__device__ ulonglong2 g_re[(size_t)TOPK * WORDS];   // sparse row entries {bits, word}
__device__ int      g_rcnt[TOPK];

// anchor widths/heights: ratio {0.5:(23,12), 1:(16,16), 2:(11,22)} x scales {8,16,32}
__constant__ float c_aw[9] = {184.f,368.f,736.f,128.f,256.f,512.f, 88.f,176.f,352.f};
__constant__ float c_ah[9] = { 96.f,192.f,384.f,128.f,256.f,512.f,176.f,352.f,704.f};

// ---------------- 1) decode + filter + key pack + score histogram ----------------
__global__ void decode_kernel(const float* __restrict__ dl, const float* __restrict__ sc)
{
    int i = blockIdx.x * blockDim.x + threadIdx.x;
    if (i >= NA) return;
    int pix = i / 9;              // h*64 + w
    int a   = i - pix * 9;
    int w   = pix & 63;
    int h   = pix >> 6;

    float s  = sc[(9 + a) * 4096 + pix];
    float d0 = dl[(a * 4 + 0) * 4096 + pix];
    float d1 = dl[(a * 4 + 1) * 4096 + pix];
    float d2 = dl[(a * 4 + 2) * 4096 + pix];
    float d3 = dl[(a * 4 + 3) * 4096 + pix];

    float aw = c_aw[a], ah = c_ah[a];
    float acx = (float)(16 * w + 8);
    float acy = (float)(16 * h + 8);

    // replicate reference fp32 op order exactly (no FMA contraction)
    float pcx = __fadd_rn(__fmul_rn(d0, aw), acx);
    float pcy = __fadd_rn(__fmul_rn(d1, ah), acy);
    float pw  = __fmul_rn(expf(d2), aw);
    float ph  = __fmul_rn(expf(d3), ah);
    float hw  = __fmul_rn(0.5f, pw);
    float hh  = __fmul_rn(0.5f, ph);

    float x1 = fminf(fmaxf(__fsub_rn(pcx, hw), 0.0f), 1023.0f);
    float y1 = fminf(fmaxf(__fsub_rn(pcy, hh), 0.0f), 1023.0f);
    float x2 = fminf(fmaxf(__fadd_rn(pcx, hw), 0.0f), 1023.0f);
    float y2 = fminf(fmaxf(__fadd_rn(pcy, hh), 0.0f), 1023.0f);

    g_props[i] = make_float4(x1, y1, x2, y2);

    bool keep = (__fadd_rn(__fsub_rn(x2, x1), 1.0f) >= 16.0f) &&
                (__fadd_rn(__fsub_rn(y2, y1), 1.0f) >= 16.0f);
    float sm = keep ? s : -CUDART_INF_F;

    unsigned b   = __float_as_uint(sm);
    unsigned ord = (b & 0x80000000u) ? ~b : (b | 0x80000000u);
    g_skey[i] = ord;
    if (keep) {
        int bin = min(NBINS - 1, (int)(s * (float)NBINS));   // s in [0,1)
        atomicAdd(&g_hist[bin], 1u);
    }
}

// ---------------- 1b) threshold bin: largest B with suffix-count >= TOPK ----------------
__global__ void thresh_kernel()
{
    __shared__ unsigned sh[NBINS];
    __shared__ int sB;
    int t = threadIdx.x;
    sh[t] = g_hist[t];
    if (t == 0) sB = 0;
    __syncthreads();
    for (int off = 1; off < NBINS; off <<= 1) {
        unsigned v = sh[t] + ((t + off < NBINS) ? sh[t + off] : 0u);
        __syncthreads();
        sh[t] = v;
        __syncthreads();
    }
    if (sh[t] >= TOPK) atomicMax(&sB, t);
    __syncthreads();
    if (t == 0) g_B = sB;
}

// ---------------- 1c) compact candidates above threshold bin ----------------
__global__ void compact_kernel()
{
    int i = blockIdx.x * blockDim.x + threadIdx.x;
    if (i >= NA) return;
    unsigned ord = g_skey[i];
    if (!(ord & 0x80000000u)) return;             // filtered (-inf)
    float s = __uint_as_float(ord & 0x7FFFFFFFu);
    int bin = min(NBINS - 1, (int)(s * (float)NBINS));
    if (bin < g_B) return;
    unsigned pos = atomicAdd(&g_hist[NBINS], 1u);
    if (pos < NCAP)
        g_k64in[pos] = ((ull)ord << 16) | (unsigned)((~i) & 0xFFFF);  // NA < 65536
}

// ---------------- 1d) O(N^2) exact rank + scatter (n-bounded) ----------------
// rank[i] = #{j<n : key_j > key_i} + #{j < i, j<n : key_j == key_i}
// Real keys unique with MSB set; padding keys are 0 -> all padding ranks = n
// (collide into slot n >= TOPK, never read by gather).
__global__ void __launch_bounds__(512) rank_kernel()
{
    __shared__ int s_rank[32];
    int tid  = threadIdx.x;
    int item = blockIdx.x * 32 + (tid & 31);       // 32 items per block
    int q    = tid >> 5;                           // 16 key segments of 512
    if (tid < 32) s_rank[tid] = 0;
    __syncthreads();

    ull ki = g_k64in[item];
    int n  = min((int)g_hist[NBINS], NCAP);
    int j0 = q * (NCAP / 16);
    int len = min(NCAP / 16, max(0, n - j0));
    int r = 0;
    #pragma unroll 4
    for (int jj = 0; jj < len; jj++) {
        int j = j0 + jj;
        ull kj = __ldg(&g_k64in[j]);               // uniform address -> broadcast
        r += (kj > ki) || ((kj == ki) && (j < item));
    }
    atomicAdd(&s_rank[tid & 31], r);
    __syncthreads();
    if (tid < 32) {
        int rk = s_rank[tid];
        if (rk < NCAP) g_k64out[rk] = ki;
    }
}

// ---------------- 2) gather top-6000 into SoA + valid bitmask ----------------
__global__ void gather_kernel()
{
    int t = blockIdx.x * blockDim.x + threadIdx.x;   // 6144 threads
    float s; float4 p = make_float4(0.f, 0.f, 0.f, 0.f);
    if (t < TOPK) {
        ull k = g_k64out[t];
        unsigned idx = (~(unsigned)k) & 0xFFFFu;
        unsigned ord = (unsigned)(k >> 16);
        unsigned b   = (ord & 0x80000000u) ? (ord & 0x7FFFFFFFu) : ~ord;
        s = __uint_as_float(b);
        if (idx < NA) p = g_props[idx];
        else s = CUDART_NAN_F;                       // padding slot
    } else s = CUDART_NAN_F;
    bool v = isfinite(s);
    unsigned bal = __ballot_sync(0xFFFFFFFFu, v);
    if ((t & 31) == 0) ((unsigned*)g_validm)[t >> 5] = bal;
    if (t < TOPK) {
        g_box[t] = p; g_bsc[t] = s;
        g_bar[t] = __fmul_rn(__fadd_rn(__fsub_rn(p.z, p.x), 1.0f),
                             __fadd_rn(__fsub_rn(p.w, p.y), 1.0f));
    }
}

// ---------------- 3) suppression bitmask tiles (4 rows/thread, guarded fast-div) ----------------
__global__ void mask_kernel()
{
    int wd = blockIdx.x;
    int rowBase = blockIdx.y * 256;
    if (rowBase >= (wd + 1) * 64) return;           // tile fully below diagonal
    int tid = threadIdx.x;

    __shared__ float4 sc4[64];
    __shared__ float  scar[64];
    int j = wd * 64 + tid;
    if (j < TOPK) { sc4[tid] = g_box[j]; scar[tid] = g_bar[j]; }
    else { sc4[tid] = make_float4(3e9f, 3e9f, -3e9f, -3e9f); scar[tid] = 1.0f; }
    __syncthreads();

    float4 rb[4]; float rar[4]; ull acc[4], allowed[4]; int irow[4]; bool valid[4];
    #pragma unroll
    for (int r = 0; r < 4; r++) {
        int i = rowBase + r * 64 + tid;
        irow[r] = i;
        bool v = (i < TOPK);
        valid[r] = v;
        rb[r]  = v ? g_box[i] : make_float4(3e9f, 3e9f, -3e9f, -3e9f);
        rar[r] = v ? g_bar[i] : 1.0f;
        int sh = i - wd * 64 + 1;                   // keep bits kk >= sh (j > i)
        allowed[r] = (sh <= 0) ? ~0ULL : (sh >= 64 ? 0ULL : (~0ULL << sh));
        acc[r] = 0ULL;
    }

    #pragma unroll 4
    for (int kk = 0; kk < 64; kk++) {
        float4 c = sc4[kk]; float car = scar[kk];
        #pragma unroll
        for (int r = 0; r < 4; r++) {
            float iw = fmaxf(__fadd_rn(__fsub_rn(fminf(rb[r].z, c.z), fmaxf(rb[r].x, c.x)), 1.0f), 0.0f);
            float ih = fmaxf(__fadd_rn(__fsub_rn(fminf(rb[r].w, c.w), fmaxf(rb[r].y, c.y)), 1.0f), 0.0f);
            float inter = __fmul_rn(iw, ih);
            float un = __fsub_rn(__fadd_rn(rar[r], car), inter);
            float t = 0.7f * un;
            bool sup;
            if (inter > t * 1.0001f)       sup = true;    // surely > 0.7
            else if (inter <= t * 0.9999f) sup = false;   // surely <= 0.7
            else sup = (__fdiv_rn(inter, un) > 0.7f);     // rare exact path
            if (sup) acc[r] |= (1ULL << kk);
        }
    }
    #pragma unroll
    for (int r = 0; r < 4; r++)
        if (valid[r]) g_mask[(size_t)irow[r] * WORDS + wd] = acc[r] & allowed[r];
}

// ---------------- 3b) compress rows to sparse entries (next superword onward) ----------------
__global__ void compress_kernel()
{
    int gi = blockIdx.x * blockDim.x + threadIdx.x;
    int i = gi >> 5, lane = gi & 31;
    if (i >= TOPK) return;
    int wlo = ((i >> 8) + 1) * 4;                   // words of NEXT superword onward
    int cnt = 0;
    for (int base = wlo; base < WORDS; base += 32) {
        int wd = base + lane;
        ull m = (wd < WORDS) ? g_mask[(size_t)i * WORDS + wd] : 0ULL;
        unsigned bal = __ballot_sync(0xFFFFFFFFu, m != 0ULL);
        if (m) g_re[(size_t)i * WORDS + cnt + __popc(bal & ((1u << lane) - 1u))] =
                   make_ulonglong2(m, (ull)wd);
        cnt += __popc(bal);
    }
    if (!lane) g_rcnt[i] = cnt;
}

// ---------------- 4) superword greedy scan: 256 candidates / iteration ----------------
__global__ void __launch_bounds__(256) scan_kernel(float* __restrict__ out)
{
    __shared__ ull removed[WPAD];
    __shared__ ull sval[WPAD];
    __shared__ ull sdiag[2][256][4];                // 16KB double-buffered diag blocks
    __shared__ ull srownz[2][4];                    // nonzero-row flags (256 bits)
    __shared__ int s_slist[POST];
    __shared__ unsigned char s_rcnt[TOPK];
    __shared__ int s_count, s_c0;
    int tid = threadIdx.x, wid = tid >> 5, lane = tid & 31;

    for (int t = tid; t < TOPK; t += 256) s_rcnt[t] = (unsigned char)g_rcnt[t];
    if (tid < WPAD) { removed[tid] = 0ULL; sval[tid] = (tid < WORDS) ? g_validm[tid] : 0ULL; }
    if (!tid) { s_count = 0; s_c0 = 0; }
    // prefetch superword 0 diag block (warps 6,7 = 64 threads)
    if (wid >= 6) {
        int t64 = tid - 192;
        #pragma unroll
        for (int kk = 0; kk < 4; kk++) {
            int r = t64 + 64 * kk;                  // row within superword; row==r for sw=0
            bool nz = false;
            #pragma unroll
            for (int k = 0; k < 4; k++) {
                ull m = 0ULL;
                if (r < TOPK && k < WORDS && k >= (r >> 6))
                    m = g_mask[(size_t)r * WORDS + k];
                sdiag[0][r][k] = m;
                nz |= (m != 0ULL);
            }
            unsigned bal = __ballot_sync(0xFFFFFFFFu, nz);
            if (!lane) ((unsigned*)&srownz[0][kk])[wid - 6] = bal;
        }
    }
    __syncthreads();

    int count = 0;
    for (int sw = 0; sw < NSW; sw++) {
        int buf = sw & 1;
        // Phase B: thread 0 resolves within-superword greedy chain (4 alive words)
        if (!tid) {
            ull a0 = sval[sw*4+0] & ~removed[sw*4+0];
            ull a1 = sval[sw*4+1] & ~removed[sw*4+1];
            ull a2 = sval[sw*4+2] & ~removed[sw*4+2];
            ull a3 = sval[sw*4+3] & ~removed[sw*4+3];
            ull rn0 = srownz[buf][0], rn1 = srownz[buf][1],
                rn2 = srownz[buf][2], rn3 = srownz[buf][3];
            int c = s_count; s_c0 = c;
            while (c < POST && (a0 | a1 | a2 | a3)) {
                int k = a0 ? 0 : (a1 ? 1 : (a2 ? 2 : 3));
                ull aw = a0 ? a0 : (a1 ? a1 : (a2 ? a2 : a3));
                int b = __ffsll(aw) - 1;
                int r = k * 64 + b;
                s_slist[c++] = sw * 256 + r;
                ull bit = 1ULL << b;
                if (k == 0) a0 &= ~bit; else if (k == 1) a1 &= ~bit;
                else if (k == 2) a2 &= ~bit; else a3 &= ~bit;
                ull rnw = (k == 0) ? rn0 : (k == 1) ? rn1 : (k == 2) ? rn2 : rn3;
                if ((rnw >> b) & 1ULL) {
                    const ull* row = sdiag[buf][r];
                    a0 &= ~row[0]; a1 &= ~row[1]; a2 &= ~row[2]; a3 &= ~row[3];
                }
            }
            s_count = c;
        }
        __syncthreads();
        count = s_count;
        int c0 = s_c0;
        if (count >= POST) break;

        // Phase C: warps 6,7 prefetch next diag block; warps 0..5 apply sparse rows,
        // one lane per kept box (192 slots) -> single memory epoch typical
        if (wid >= 6) {
            if (sw + 1 < NSW) {
                int t64 = tid - 192;
                #pragma unroll
                for (int kk = 0; kk < 4; kk++) {
                    int r = t64 + 64 * kk;
                    int row = (sw + 1) * 256 + r;
                    bool nz = false;
                    #pragma unroll
                    for (int k = 0; k < 4; k++) {
                        int w = (sw + 1) * 4 + k;
                        ull m = 0ULL;
                        if (row < TOPK && w < WORDS && w >= (row >> 6))
                            m = g_mask[(size_t)row * WORDS + w];
                        sdiag[buf ^ 1][r][k] = m;
                        nz |= (m != 0ULL);
                    }
                    unsigned bal = __ballot_sync(0xFFFFFFFFu, nz);
                    if (!lane) ((unsigned*)&srownz[buf ^ 1][kk])[wid - 6] = bal;
                }
            }
        } else {
            int nk = count - c0;
            for (int slot = tid; slot < nk; slot += 192) {
                int idx = s_slist[c0 + slot];
                int cnt = s_rcnt[idx];
                const ulonglong2* re = &g_re[(size_t)idx * WORDS];
                for (int e = 0; e < cnt; e++) {
                    ulonglong2 ent = re[e];
                    atomicOr(&removed[(int)ent.y], ent.x);
                }
            }
        }
        __syncthreads();
    }

    // output
    int total = min(count, POST);
    float* outs = out + POST * 5;
    for (int t = tid; t < total; t += 256) {
        int i = s_slist[t];
        float4 p = g_box[i];
        out[t * 5 + 1] = p.x; out[t * 5 + 2] = p.y;
        out[t * 5 + 3] = p.z; out[t * 5 + 4] = p.w;
        outs[t] = g_bsc[i];
    }
}

// ---------------- launch ----------------
extern "C" void kernel_launch(void* const* d_in, const int* in_sizes, int n_in,
                              void* d_out, int out_size)
{
    const float* deltas = (const float*)d_in[0];
    const float* scores = (const float*)d_in[1];

    cudaMemsetAsync(d_out, 0, (size_t)out_size * sizeof(float), 0);
    void* p;
    cudaGetSymbolAddress(&p, g_hist);  cudaMemsetAsync(p, 0, sizeof(g_hist), 0);
    cudaGetSymbolAddress(&p, g_k64in); cudaMemsetAsync(p, 0, sizeof(g_k64in), 0);

    decode_kernel<<<NA / 256, 256>>>(deltas, scores);
    thresh_kernel<<<1, NBINS>>>();
    compact_kernel<<<NA / 256, 256>>>();
    rank_kernel<<<NCAP / 32, 512>>>();               // 256 blocks, 512 threads
    gather_kernel<<<24, 256>>>();                    // 6144 threads

    mask_kernel<<<dim3(WORDS, (TOPK + 255) / 256), 64>>>();
    compress_kernel<<<TOPK * 32 / 256, 256>>>();
    scan_kernel<<<1, 256>>>((float*)d_out);
}

// round 12
// speedup vs baseline: 1.6063x; 1.6063x over previous
#include <cuda_runtime.h>
#include <math_constants.h>
#include <cstdint>

#define NA    36864      // 64*64*9 proposals
#define TOPK  6000
#define POST  2000
#define WORDS 94         // ceil(6000/64)
#define WPAD  96
#define NCAP  8192       // compacted capacity (power of two)
#define NBINS 1024

typedef unsigned long long ull;

// ---------------- static device scratch (no allocations allowed) ----------------
__device__ float4   g_props[NA];
__device__ unsigned g_skey[NA];
__device__ unsigned g_hist[NBINS + 1];      // [NBINS] = compact counter
__device__ int      g_B;
__device__ ull      g_k64in[NCAP], g_k64out[NCAP];
__device__ float4   g_box[TOPK];
__device__ float    g_bar[TOPK], g_bsc[TOPK];
__device__ ull      g_validm[96];
__device__ ull      g_mask[(size_t)TOPK * WORDS];
__device__ ulonglong2 g_re[(size_t)TOPK * WORDS];   // sparse row entries {bits, word}
__device__ int      g_rcnt[TOPK];

// anchor widths/heights: ratio {0.5:(23,12), 1:(16,16), 2:(11,22)} x scales {8,16,32}
__constant__ float c_aw[9] = {184.f,368.f,736.f,128.f,256.f,512.f, 88.f,176.f,352.f};
__constant__ float c_ah[9] = { 96.f,192.f,384.f,128.f,256.f,512.f,176.f,352.f,704.f};

// ---------------- 1) decode + filter + key pack + score histogram ----------------
__global__ void decode_kernel(const float* __restrict__ dl, const float* __restrict__ sc)
{
    int i = blockIdx.x * blockDim.x + threadIdx.x;
    if (i >= NA) return;
    int pix = i / 9;              // h*64 + w
    int a   = i - pix * 9;
    int w   = pix & 63;
    int h   = pix >> 6;

    float s  = sc[(9 + a) * 4096 + pix];
    float d0 = dl[(a * 4 + 0) * 4096 + pix];
    float d1 = dl[(a * 4 + 1) * 4096 + pix];
    float d2 = dl[(a * 4 + 2) * 4096 + pix];
    float d3 = dl[(a * 4 + 3) * 4096 + pix];

    float aw = c_aw[a], ah = c_ah[a];
    float acx = (float)(16 * w + 8);
    float acy = (float)(16 * h + 8);

    // replicate reference fp32 op order exactly (no FMA contraction)
    float pcx = __fadd_rn(__fmul_rn(d0, aw), acx);
    float pcy = __fadd_rn(__fmul_rn(d1, ah), acy);
    float pw  = __fmul_rn(expf(d2), aw);
    float ph  = __fmul_rn(expf(d3), ah);
    float hw  = __fmul_rn(0.5f, pw);
    float hh  = __fmul_rn(0.5f, ph);

    float x1 = fminf(fmaxf(__fsub_rn(pcx, hw), 0.0f), 1023.0f);
    float y1 = fminf(fmaxf(__fsub_rn(pcy, hh), 0.0f), 1023.0f);
    float x2 = fminf(fmaxf(__fadd_rn(pcx, hw), 0.0f), 1023.0f);
    float y2 = fminf(fmaxf(__fadd_rn(pcy, hh), 0.0f), 1023.0f);

    g_props[i] = make_float4(x1, y1, x2, y2);

    bool keep = (__fadd_rn(__fsub_rn(x2, x1), 1.0f) >= 16.0f) &&
                (__fadd_rn(__fsub_rn(y2, y1), 1.0f) >= 16.0f);
    float sm = keep ? s : -CUDART_INF_F;

    unsigned b   = __float_as_uint(sm);
    unsigned ord = (b & 0x80000000u) ? ~b : (b | 0x80000000u);
    g_skey[i] = ord;
    if (keep) {
        int bin = min(NBINS - 1, (int)(s * (float)NBINS));   // s in [0,1)
        atomicAdd(&g_hist[bin], 1u);
    }
}

// ---------------- 1b) threshold bin: largest B with suffix-count >= TOPK ----------------
__global__ void thresh_kernel()
{
    __shared__ unsigned sh[NBINS];
    __shared__ int sB;
    int t = threadIdx.x;
    sh[t] = g_hist[t];
    if (t == 0) sB = 0;
    __syncthreads();
    for (int off = 1; off < NBINS; off <<= 1) {
        unsigned v = sh[t] + ((t + off < NBINS) ? sh[t + off] : 0u);
        __syncthreads();
        sh[t] = v;
        __syncthreads();
    }
    if (sh[t] >= TOPK) atomicMax(&sB, t);
    __syncthreads();
    if (t == 0) g_B = sB;
}

// ---------------- 1c) compact candidates above threshold bin ----------------
__global__ void compact_kernel()
{
    int i = blockIdx.x * blockDim.x + threadIdx.x;
    if (i >= NA) return;
    unsigned ord = g_skey[i];
    if (!(ord & 0x80000000u)) return;             // filtered (-inf)
    float s = __uint_as_float(ord & 0x7FFFFFFFu);
    int bin = min(NBINS - 1, (int)(s * (float)NBINS));
    if (bin < g_B) return;
    unsigned pos = atomicAdd(&g_hist[NBINS], 1u);
    if (pos < NCAP)
        g_k64in[pos] = ((ull)ord << 16) | (unsigned)((~i) & 0xFFFF);  // NA < 65536
}

// ---------------- 1d) O(N^2) exact rank + scatter (R10 known-good version) ----------------
// rank[i] = #{j : key_j > key_i} + #{j < i : key_j == key_i}  (padding zeros tie-broken)
__global__ void __launch_bounds__(512) rank_kernel()
{
    __shared__ int s_rank[32];
    int tid  = threadIdx.x;
    int item = blockIdx.x * 32 + (tid & 31);       // 32 items per block
    int q    = tid >> 5;                           // 16 key segments of 512
    if (tid < 32) s_rank[tid] = 0;
    __syncthreads();

    ull ki = g_k64in[item];
    int j0 = q * (NCAP / 16);
    int r = 0;
    #pragma unroll 8
    for (int jj = 0; jj < NCAP / 16; jj++) {
        int j = j0 + jj;
        ull kj = __ldg(&g_k64in[j]);               // uniform address -> broadcast
        r += (kj > ki) || ((kj == ki) && (j < item));
    }
    atomicAdd(&s_rank[tid & 31], r);
    __syncthreads();
    if (tid < 32) g_k64out[s_rank[tid]] = ki;      // ranks form a permutation
}

// ---------------- 2) gather top-6000 into SoA + valid bitmask ----------------
__global__ void gather_kernel()
{
    int t = blockIdx.x * blockDim.x + threadIdx.x;   // 6144 threads
    float s; float4 p = make_float4(0.f, 0.f, 0.f, 0.f);
    if (t < TOPK) {
        ull k = g_k64out[t];
        unsigned idx = (~(unsigned)k) & 0xFFFFu;
        unsigned ord = (unsigned)(k >> 16);
        unsigned b   = (ord & 0x80000000u) ? (ord & 0x7FFFFFFFu) : ~ord;
        s = __uint_as_float(b);
        if (idx < NA) p = g_props[idx];
        else s = CUDART_NAN_F;                       // padding slot
    } else s = CUDART_NAN_F;
    bool v = isfinite(s);
    unsigned bal = __ballot_sync(0xFFFFFFFFu, v);
    if ((t & 31) == 0) ((unsigned*)g_validm)[t >> 5] = bal;
    if (t < TOPK) {
        g_box[t] = p; g_bsc[t] = s;
        g_bar[t] = __fmul_rn(__fadd_rn(__fsub_rn(p.z, p.x), 1.0f),
                             __fadd_rn(__fsub_rn(p.w, p.y), 1.0f));
    }
}

// ---------------- 3) suppression bitmask tiles (4 rows/thread, guarded fast-div) ----------------
__global__ void mask_kernel()
{
    int wd = blockIdx.x;
    int rowBase = blockIdx.y * 256;
    if (rowBase >= (wd + 1) * 64) return;           // tile fully below diagonal
    int tid = threadIdx.x;

    __shared__ float4 sc4[64];
    __shared__ float  scar[64];
    int j = wd * 64 + tid;
    if (j < TOPK) { sc4[tid] = g_box[j]; scar[tid] = g_bar[j]; }
    else { sc4[tid] = make_float4(3e9f, 3e9f, -3e9f, -3e9f); scar[tid] = 1.0f; }
    __syncthreads();

    float4 rb[4]; float rar[4]; ull acc[4], allowed[4]; int irow[4]; bool valid[4];
    #pragma unroll
    for (int r = 0; r < 4; r++) {
        int i = rowBase + r * 64 + tid;
        irow[r] = i;
        bool v = (i < TOPK);
        valid[r] = v;
        rb[r]  = v ? g_box[i] : make_float4(3e9f, 3e9f, -3e9f, -3e9f);
        rar[r] = v ? g_bar[i] : 1.0f;
        int sh = i - wd * 64 + 1;                   // keep bits kk >= sh (j > i)
        allowed[r] = (sh <= 0) ? ~0ULL : (sh >= 64 ? 0ULL : (~0ULL << sh));
        acc[r] = 0ULL;
    }

    #pragma unroll 4
    for (int kk = 0; kk < 64; kk++) {
        float4 c = sc4[kk]; float car = scar[kk];
        #pragma unroll
        for (int r = 0; r < 4; r++) {
            float iw = fmaxf(__fadd_rn(__fsub_rn(fminf(rb[r].z, c.z), fmaxf(rb[r].x, c.x)), 1.0f), 0.0f);
            float ih = fmaxf(__fadd_rn(__fsub_rn(fminf(rb[r].w, c.w), fmaxf(rb[r].y, c.y)), 1.0f), 0.0f);
            float inter = __fmul_rn(iw, ih);
            float un = __fsub_rn(__fadd_rn(rar[r], car), inter);
            float t = 0.7f * un;
            bool sup;
            if (inter > t * 1.0001f)       sup = true;    // surely > 0.7
            else if (inter <= t * 0.9999f) sup = false;   // surely <= 0.7
            else sup = (__fdiv_rn(inter, un) > 0.7f);     // rare exact path
            if (sup) acc[r] |= (1ULL << kk);
        }
    }
    #pragma unroll
    for (int r = 0; r < 4; r++)
        if (valid[r]) g_mask[(size_t)irow[r] * WORDS + wd] = acc[r] & allowed[r];
}

// ---------------- 3b) compress rows to sparse entries (own word + 2 onward) ----------------
// wd == own_word   : handled by scan's diag block
// wd == own_word+1 : handled by scan's next-column (urgent, shared-only)
__global__ void compress_kernel()
{
    int gi = blockIdx.x * blockDim.x + threadIdx.x;
    int i = gi >> 5, lane = gi & 31;
    if (i >= TOPK) return;
    int wlo = (i >> 6) + 2;
    int cnt = 0;
    for (int base = wlo; base < WORDS; base += 32) {
        int wd = base + lane;
        ull m = (wd < WORDS) ? g_mask[(size_t)i * WORDS + wd] : 0ULL;
        unsigned bal = __ballot_sync(0xFFFFFFFFu, m != 0ULL);
        if (m) g_re[(size_t)i * WORDS + cnt + __popc(bal & ((1u << lane) - 1u))] =
                   make_ulonglong2(m, (ull)wd);
        cnt += __popc(bal);
    }
    if (!lane) g_rcnt[i] = cnt;
}

// ---------------- 4) pipelined greedy scan: deferred suppression off critical path ----------------
// Per word w (ONE barrier each):
//   thread 0     : Phase B chain (diag in shared) + urgent next-word OR (nextcol in shared)
//   warps 1..4   : apply K_{w-1}'s deferred entries (all target words >= w+1; atomics)
//   warps 6,7    : prefetch diag + nextcol of word w+1
__global__ void __launch_bounds__(256) scan_kernel(float* __restrict__ out)
{
    __shared__ ull removed[WPAD];
    __shared__ ull sval[WPAD];
    __shared__ ull sdiag[2][64];
    __shared__ ull snext[2][64];
    __shared__ unsigned s_rownz[2][2];
    __shared__ int s_slist[POST];
    __shared__ unsigned char s_rcnt[TOPK];
    __shared__ int s_count, s_c0;
    int tid = threadIdx.x, wid = tid >> 5, lane = tid & 31;

    for (int t = tid; t < TOPK; t += 256) s_rcnt[t] = (unsigned char)g_rcnt[t];
    if (tid < WPAD) { removed[tid] = 0ULL; sval[tid] = (tid < WORDS) ? g_validm[tid] : 0ULL; }
    if (!tid) { s_count = 0; s_c0 = 0; }
    if (wid >= 6) {                                  // prefetch word 0 diag + nextcol
        int t = tid - 192;
        ull dm = g_mask[(size_t)t * WORDS + 0];
        sdiag[0][t] = dm;
        snext[0][t] = g_mask[(size_t)t * WORDS + 1];
        unsigned bal = __ballot_sync(0xFFFFFFFFu, dm != 0ULL);
        if (!lane) s_rownz[0][wid - 6] = bal;
    }
    __syncthreads();

    int count = 0, klo = 0, khi = 0;
    for (int w = 0; w < WORDS; w++) {
        int buf = w & 1;
        if (!tid) {
            // Phase B: greedy chain within word w, accumulate urgent next-word suppression
            ull alive = sval[w] & ~removed[w];
            ull rn = ((ull)s_rownz[buf][1] << 32) | s_rownz[buf][0];
            const ull* diag = sdiag[buf];
            const ull* nxt  = snext[buf];
            ull urg = 0ULL;
            int c = s_count; s_c0 = c;
            while (alive && c < POST) {
                int b = __ffsll(alive) - 1;
                ull bit = 1ULL << b;
                s_slist[c++] = w * 64 + b;
                alive &= ~bit;
                if (rn & bit) alive &= ~diag[b];
                urg |= nxt[b];
            }
            s_count = c;
            if (urg && w + 1 < WORDS) atomicOr(&removed[w + 1], urg);
        } else if (wid >= 6) {
            // prefetch diag + nextcol for word w+1
            if (w + 1 < WORDS) {
                int t = tid - 192;
                int row = (w + 1) * 64 + t;
                ull dm = 0ULL, nm = 0ULL;
                if (row < TOPK) {
                    dm = g_mask[(size_t)row * WORDS + (w + 1)];
                    if (w + 2 < WORDS) nm = g_mask[(size_t)row * WORDS + (w + 2)];
                }
                sdiag[buf ^ 1][t] = dm;
                snext[buf ^ 1][t] = nm;
                unsigned bal = __ballot_sync(0xFFFFFFFFu, dm != 0ULL);
                if (!lane) s_rownz[buf ^ 1][wid - 6] = bal;
            }
        } else if (tid >= 32 && tid < 160) {
            // deferred application of K_{w-1}: 2 lanes per kept box
            int nk = khi - klo;
            int slot = (tid - 32) >> 1;
            if (slot < nk) {
                int idx = s_slist[klo + slot];
                int cnt = s_rcnt[idx];
                for (int e = ((tid - 32) & 1); e < cnt; e += 2) {
                    ulonglong2 ent = g_re[(size_t)idx * WORDS + e];
                    atomicOr(&removed[(int)ent.y], ent.x);
                }
            }
        }
        __syncthreads();
        klo = s_c0; khi = s_count; count = s_count;
        if (count >= POST) break;
    }

    // output
    int total = min(count, POST);
    float* outs = out + POST * 5;
    for (int t = tid; t < total; t += 256) {
        int i = s_slist[t];
        float4 p = g_box[i];
        out[t * 5 + 1] = p.x; out[t * 5 + 2] = p.y;
        out[t * 5 + 3] = p.z; out[t * 5 + 4] = p.w;
        outs[t] = g_bsc[i];
    }
}

// ---------------- launch ----------------
extern "C" void kernel_launch(void* const* d_in, const int* in_sizes, int n_in,
                              void* d_out, int out_size)
{
    const float* deltas = (const float*)d_in[0];
    const float* scores = (const float*)d_in[1];

    cudaMemsetAsync(d_out, 0, (size_t)out_size * sizeof(float), 0);
    void* p;
    cudaGetSymbolAddress(&p, g_hist);  cudaMemsetAsync(p, 0, sizeof(g_hist), 0);
    cudaGetSymbolAddress(&p, g_k64in); cudaMemsetAsync(p, 0, sizeof(g_k64in), 0);

    decode_kernel<<<NA / 256, 256>>>(deltas, scores);
    thresh_kernel<<<1, NBINS>>>();
    compact_kernel<<<NA / 256, 256>>>();
    rank_kernel<<<NCAP / 32, 512>>>();               // 256 blocks, 512 threads
    gather_kernel<<<24, 256>>>();                    // 6144 threads

    mask_kernel<<<dim3(WORDS, (TOPK + 255) / 256), 64>>>();
    compress_kernel<<<TOPK * 32 / 256, 256>>>();
    scan_kernel<<<1, 256>>>((float*)d_out);
}

// round 13
// speedup vs baseline: 1.7335x; 1.0792x over previous
#include <cuda_runtime.h>
#include <math_constants.h>
#include <cstdint>

#define NA    36864      // 64*64*9 proposals
#define TOPK  6000
#define POST  2000
#define WORDS 94         // ceil(6000/64)
#define WPAD  96
#define NCAP  8192       // compacted capacity (power of two)
#define NBINS 1024

typedef unsigned long long ull;

// ---------------- static device scratch (no allocations allowed) ----------------
__device__ float4   g_props[NA];
__device__ unsigned g_skey[NA];
__device__ unsigned g_hist[NBINS + 1];      // [NBINS] = compact counter
__device__ int      g_B;
__device__ ull      g_k64in[NCAP], g_k64out[NCAP];
__device__ float4   g_box[TOPK];
__device__ float    g_bar[TOPK], g_bsc[TOPK];
__device__ ull      g_validm[96];
__device__ ull      g_mask[(size_t)TOPK * WORDS];
__device__ ulonglong2 g_re[(size_t)TOPK * WORDS];   // sparse row entries {bits, word}
__device__ int      g_rcnt[TOPK];

// anchor widths/heights: ratio {0.5:(23,12), 1:(16,16), 2:(11,22)} x scales {8,16,32}
__constant__ float c_aw[9] = {184.f,368.f,736.f,128.f,256.f,512.f, 88.f,176.f,352.f};
__constant__ float c_ah[9] = { 96.f,192.f,384.f,128.f,256.f,512.f,176.f,352.f,704.f};

// ---------------- 1) decode + filter + key pack + score histogram ----------------
__global__ void decode_kernel(const float* __restrict__ dl, const float* __restrict__ sc)
{
    int i = blockIdx.x * blockDim.x + threadIdx.x;
    if (i >= NA) return;
    int pix = i / 9;              // h*64 + w
    int a   = i - pix * 9;
    int w   = pix & 63;
    int h   = pix >> 6;

    float s  = sc[(9 + a) * 4096 + pix];
    float d0 = dl[(a * 4 + 0) * 4096 + pix];
    float d1 = dl[(a * 4 + 1) * 4096 + pix];
    float d2 = dl[(a * 4 + 2) * 4096 + pix];
    float d3 = dl[(a * 4 + 3) * 4096 + pix];

    float aw = c_aw[a], ah = c_ah[a];
    float acx = (float)(16 * w + 8);
    float acy = (float)(16 * h + 8);

    // replicate reference fp32 op order exactly (no FMA contraction)
    float pcx = __fadd_rn(__fmul_rn(d0, aw), acx);
    float pcy = __fadd_rn(__fmul_rn(d1, ah), acy);
    float pw  = __fmul_rn(expf(d2), aw);
    float ph  = __fmul_rn(expf(d3), ah);
    float hw  = __fmul_rn(0.5f, pw);
    float hh  = __fmul_rn(0.5f, ph);

    float x1 = fminf(fmaxf(__fsub_rn(pcx, hw), 0.0f), 1023.0f);
    float y1 = fminf(fmaxf(__fsub_rn(pcy, hh), 0.0f), 1023.0f);
    float x2 = fminf(fmaxf(__fadd_rn(pcx, hw), 0.0f), 1023.0f);
    float y2 = fminf(fmaxf(__fadd_rn(pcy, hh), 0.0f), 1023.0f);

    g_props[i] = make_float4(x1, y1, x2, y2);

    bool keep = (__fadd_rn(__fsub_rn(x2, x1), 1.0f) >= 16.0f) &&
                (__fadd_rn(__fsub_rn(y2, y1), 1.0f) >= 16.0f);
    float sm = keep ? s : -CUDART_INF_F;

    unsigned b   = __float_as_uint(sm);
    unsigned ord = (b & 0x80000000u) ? ~b : (b | 0x80000000u);
    g_skey[i] = ord;
    if (keep) {
        int bin = min(NBINS - 1, (int)(s * (float)NBINS));   // s in [0,1)
        atomicAdd(&g_hist[bin], 1u);
    }
}

// ---------------- 1b) threshold bin: largest B with suffix-count >= TOPK ----------------
__global__ void thresh_kernel()
{
    __shared__ unsigned sh[NBINS];
    __shared__ int sB;
    int t = threadIdx.x;
    sh[t] = g_hist[t];
    if (t == 0) sB = 0;
    __syncthreads();
    for (int off = 1; off < NBINS; off <<= 1) {
        unsigned v = sh[t] + ((t + off < NBINS) ? sh[t + off] : 0u);
        __syncthreads();
        sh[t] = v;
        __syncthreads();
    }
    if (sh[t] >= TOPK) atomicMax(&sB, t);
    __syncthreads();
    if (t == 0) g_B = sB;
}

// ---------------- 1c) compact candidates above threshold bin ----------------
__global__ void compact_kernel()
{
    int i = blockIdx.x * blockDim.x + threadIdx.x;
    if (i >= NA) return;
    unsigned ord = g_skey[i];
    if (!(ord & 0x80000000u)) return;             // filtered (-inf)
    float s = __uint_as_float(ord & 0x7FFFFFFFu);
    int bin = min(NBINS - 1, (int)(s * (float)NBINS));
    if (bin < g_B) return;
    unsigned pos = atomicAdd(&g_hist[NBINS], 1u);
    if (pos < NCAP)
        g_k64in[pos] = ((ull)ord << 16) | (unsigned)((~i) & 0xFFFF);  // NA < 65536
}

// ---------------- 1d) O(N^2) exact rank + scatter ----------------
// rank[i] = #{j : key_j > key_i} + #{j < i : key_j == key_i}  (padding zeros tie-broken)
__global__ void __launch_bounds__(512) rank_kernel()
{
    __shared__ int s_rank[32];
    int tid  = threadIdx.x;
    int item = blockIdx.x * 32 + (tid & 31);       // 32 items per block
    int q    = tid >> 5;                           // 16 key segments of 512
    if (tid < 32) s_rank[tid] = 0;
    __syncthreads();

    ull ki = g_k64in[item];
    int j0 = q * (NCAP / 16);
    int r = 0;
    #pragma unroll 8
    for (int jj = 0; jj < NCAP / 16; jj++) {
        int j = j0 + jj;
        ull kj = __ldg(&g_k64in[j]);               // uniform address -> broadcast
        r += (kj > ki) || ((kj == ki) && (j < item));
    }
    atomicAdd(&s_rank[tid & 31], r);
    __syncthreads();
    if (tid < 32) g_k64out[s_rank[tid]] = ki;      // ranks form a permutation
}

// ---------------- 2) gather top-6000 into SoA + valid bitmask ----------------
__global__ void gather_kernel()
{
    int t = blockIdx.x * blockDim.x + threadIdx.x;   // 6144 threads
    float s; float4 p = make_float4(0.f, 0.f, 0.f, 0.f);
    if (t < TOPK) {
        ull k = g_k64out[t];
        unsigned idx = (~(unsigned)k) & 0xFFFFu;
        unsigned ord = (unsigned)(k >> 16);
        unsigned b   = (ord & 0x80000000u) ? (ord & 0x7FFFFFFFu) : ~ord;
        s = __uint_as_float(b);
        if (idx < NA) p = g_props[idx];
        else s = CUDART_NAN_F;                       // padding slot
    } else s = CUDART_NAN_F;
    bool v = isfinite(s);
    unsigned bal = __ballot_sync(0xFFFFFFFFu, v);
    if ((t & 31) == 0) ((unsigned*)g_validm)[t >> 5] = bal;
    if (t < TOPK) {
        g_box[t] = p; g_bsc[t] = s;
        g_bar[t] = __fmul_rn(__fadd_rn(__fsub_rn(p.z, p.x), 1.0f),
                             __fadd_rn(__fsub_rn(p.w, p.y), 1.0f));
    }
}

// ---------------- 3) suppression bitmask tiles (4 rows/thread, guarded fast-div) ----------------
__global__ void mask_kernel()
{
    int wd = blockIdx.x;
    int rowBase = blockIdx.y * 256;
    if (rowBase >= (wd + 1) * 64) return;           // tile fully below diagonal
    int tid = threadIdx.x;

    __shared__ float4 sc4[64];
    __shared__ float  scar[64];
    int j = wd * 64 + tid;
    if (j < TOPK) { sc4[tid] = g_box[j]; scar[tid] = g_bar[j]; }
    else { sc4[tid] = make_float4(3e9f, 3e9f, -3e9f, -3e9f); scar[tid] = 1.0f; }
    __syncthreads();

    float4 rb[4]; float rar[4]; ull acc[4], allowed[4]; int irow[4]; bool valid[4];
    #pragma unroll
    for (int r = 0; r < 4; r++) {
        int i = rowBase + r * 64 + tid;
        irow[r] = i;
        bool v = (i < TOPK);
        valid[r] = v;
        rb[r]  = v ? g_box[i] : make_float4(3e9f, 3e9f, -3e9f, -3e9f);
        rar[r] = v ? g_bar[i] : 1.0f;
        int sh = i - wd * 64 + 1;                   // keep bits kk >= sh (j > i)
        allowed[r] = (sh <= 0) ? ~0ULL : (sh >= 64 ? 0ULL : (~0ULL << sh));
        acc[r] = 0ULL;
    }

    #pragma unroll 4
    for (int kk = 0; kk < 64; kk++) {
        float4 c = sc4[kk]; float car = scar[kk];
        #pragma unroll
        for (int r = 0; r < 4; r++) {
            float iw = fmaxf(__fadd_rn(__fsub_rn(fminf(rb[r].z, c.z), fmaxf(rb[r].x, c.x)), 1.0f), 0.0f);
            float ih = fmaxf(__fadd_rn(__fsub_rn(fminf(rb[r].w, c.w), fmaxf(rb[r].y, c.y)), 1.0f), 0.0f);
            float inter = __fmul_rn(iw, ih);
            float un = __fsub_rn(__fadd_rn(rar[r], car), inter);
            float t = 0.7f * un;
            bool sup;
            if (inter > t * 1.0001f)       sup = true;    // surely > 0.7
            else if (inter <= t * 0.9999f) sup = false;   // surely <= 0.7
            else sup = (__fdiv_rn(inter, un) > 0.7f);     // rare exact path
            if (sup) acc[r] |= (1ULL << kk);
        }
    }
    #pragma unroll
    for (int r = 0; r < 4; r++)
        if (valid[r]) g_mask[(size_t)irow[r] * WORDS + wd] = acc[r] & allowed[r];
}

// ---------------- 3b) compress rows to sparse entries (own word + 2 onward) ----------------
// wd == own_word   : handled by scan's diag block
// wd == own_word+1 : handled by scan's next-column (urgent, shared-only)
__global__ void compress_kernel()
{
    int gi = blockIdx.x * blockDim.x + threadIdx.x;
    int i = gi >> 5, lane = gi & 31;
    if (i >= TOPK) return;
    int wlo = (i >> 6) + 2;
    int cnt = 0;
    for (int base = wlo; base < WORDS; base += 32) {
        int wd = base + lane;
        ull m = (wd < WORDS) ? g_mask[(size_t)i * WORDS + wd] : 0ULL;
        unsigned bal = __ballot_sync(0xFFFFFFFFu, m != 0ULL);
        if (m) g_re[(size_t)i * WORDS + cnt + __popc(bal & ((1u << lane) - 1u))] =
                   make_ulonglong2(m, (ull)wd);
        cnt += __popc(bal);
    }
    if (!lane) g_rcnt[i] = cnt;
}

// ---------------- 4) pipelined greedy scan: batched-MLP deferred suppression ----------------
// Per word w (ONE barrier each):
//   thread 0     : Phase B chain (diag in shared) + urgent next-word OR (nextcol in shared)
//   warps 1..5   : apply K_{w-1}'s deferred entries (target words >= w+1), 4 lanes/box,
//                  4 entries loaded per lane-iteration with independent LDGs (MLP)
//   warps 6,7    : prefetch diag + nextcol of word w+1
__global__ void __launch_bounds__(256) scan_kernel(float* __restrict__ out)
{
    __shared__ ull removed[WPAD];
    __shared__ ull sval[WPAD];
    __shared__ ull sdiag[2][64];
    __shared__ ull snext[2][64];
    __shared__ unsigned s_rownz[2][2];
    __shared__ int s_slist[POST];
    __shared__ unsigned char s_rcnt[TOPK];
    __shared__ int s_count, s_c0;
    int tid = threadIdx.x, wid = tid >> 5, lane = tid & 31;

    for (int t = tid; t < TOPK; t += 256) s_rcnt[t] = (unsigned char)g_rcnt[t];
    if (tid < WPAD) { removed[tid] = 0ULL; sval[tid] = (tid < WORDS) ? g_validm[tid] : 0ULL; }
    if (!tid) { s_count = 0; s_c0 = 0; }
    if (wid >= 6) {                                  // prefetch word 0 diag + nextcol
        int t = tid - 192;
        ull dm = g_mask[(size_t)t * WORDS + 0];
        sdiag[0][t] = dm;
        snext[0][t] = g_mask[(size_t)t * WORDS + 1];
        unsigned bal = __ballot_sync(0xFFFFFFFFu, dm != 0ULL);
        if (!lane) s_rownz[0][wid - 6] = bal;
    }
    __syncthreads();

    int count = 0, klo = 0, khi = 0;
    for (int w = 0; w < WORDS; w++) {
        int buf = w & 1;
        if (!tid) {
            // Phase B: greedy chain within word w, accumulate urgent next-word suppression
            ull alive = sval[w] & ~removed[w];
            ull rn = ((ull)s_rownz[buf][1] << 32) | s_rownz[buf][0];
            const ull* diag = sdiag[buf];
            const ull* nxt  = snext[buf];
            ull urg = 0ULL;
            int c = s_count; s_c0 = c;
            while (alive && c < POST) {
                int b = __ffsll(alive) - 1;
                ull bit = 1ULL << b;
                s_slist[c++] = w * 64 + b;
                alive &= ~bit;
                if (rn & bit) alive &= ~diag[b];
                urg |= nxt[b];
            }
            s_count = c;
            if (urg && w + 1 < WORDS) atomicOr(&removed[w + 1], urg);
        } else if (wid >= 6) {
            // prefetch diag + nextcol for word w+1
            if (w + 1 < WORDS) {
                int t = tid - 192;
                int row = (w + 1) * 64 + t;
                ull dm = 0ULL, nm = 0ULL;
                if (row < TOPK) {
                    dm = g_mask[(size_t)row * WORDS + (w + 1)];
                    if (w + 2 < WORDS) nm = g_mask[(size_t)row * WORDS + (w + 2)];
                }
                sdiag[buf ^ 1][t] = dm;
                snext[buf ^ 1][t] = nm;
                unsigned bal = __ballot_sync(0xFFFFFFFFu, dm != 0ULL);
                if (!lane) s_rownz[buf ^ 1][wid - 6] = bal;
            }
        } else if (tid >= 32) {
            // deferred K_{w-1}: 160 threads, 4 lanes/box (40 slots), 4-deep batched loads
            int t = tid - 32;
            int nk = khi - klo;
            for (int slot = t >> 2; slot < nk; slot += 40) {
                int idx = s_slist[klo + slot];
                int cnt = s_rcnt[idx];
                const ulonglong2* re = &g_re[(size_t)idx * WORDS];
                for (int e = (t & 3); e < cnt; e += 16) {
                    ulonglong2 e0 = re[e];
                    ulonglong2 e1, e2, e3;
                    bool b1 = (e + 4) < cnt, b2 = (e + 8) < cnt, b3 = (e + 12) < cnt;
                    if (b1) e1 = re[e + 4];
                    if (b2) e2 = re[e + 8];
                    if (b3) e3 = re[e + 12];
                    atomicOr(&removed[(int)e0.y], e0.x);
                    if (b1) atomicOr(&removed[(int)e1.y], e1.x);
                    if (b2) atomicOr(&removed[(int)e2.y], e2.x);
                    if (b3) atomicOr(&removed[(int)e3.y], e3.x);
                }
            }
        }
        __syncthreads();
        klo = s_c0; khi = s_count; count = s_count;
        if (count >= POST) break;
    }

    // output
    int total = min(count, POST);
    float* outs = out + POST * 5;
    for (int t = tid; t < total; t += 256) {
        int i = s_slist[t];
        float4 p = g_box[i];
        out[t * 5 + 1] = p.x; out[t * 5 + 2] = p.y;
        out[t * 5 + 3] = p.z; out[t * 5 + 4] = p.w;
        outs[t] = g_bsc[i];
    }
}

// ---------------- launch ----------------
extern "C" void kernel_launch(void* const* d_in, const int* in_sizes, int n_in,
                              void* d_out, int out_size)
{
    const float* deltas = (const float*)d_in[0];
    const float* scores = (const float*)d_in[1];

    cudaMemsetAsync(d_out, 0, (size_t)out_size * sizeof(float), 0);
    void* p;
    cudaGetSymbolAddress(&p, g_hist);  cudaMemsetAsync(p, 0, sizeof(g_hist), 0);
    cudaGetSymbolAddress(&p, g_k64in); cudaMemsetAsync(p, 0, sizeof(g_k64in), 0);

    decode_kernel<<<NA / 256, 256>>>(deltas, scores);
    thresh_kernel<<<1, NBINS>>>();
    compact_kernel<<<NA / 256, 256>>>();
    rank_kernel<<<NCAP / 32, 512>>>();               // 256 blocks, 512 threads
    gather_kernel<<<24, 256>>>();                    // 6144 threads

    mask_kernel<<<dim3(WORDS, (TOPK + 255) / 256), 64>>>();
    compress_kernel<<<TOPK * 32 / 256, 256>>>();
    scan_kernel<<<1, 256>>>((float*)d_out);
}

// round 14
// speedup vs baseline: 1.8704x; 1.0790x over previous
#include <cuda_runtime.h>
#include <math_constants.h>
#include <cstdint>

#define NA    36864      // 64*64*9 proposals
#define TOPK  6000
#define POST  2000
#define WORDS 94         // ceil(6000/64)
#define WPAD  96
#define NCAP  6144       // compacted capacity (suffix(B) < 6000 + count(B) << 6144)
#define NBINS 1024

typedef unsigned long long ull;

// ---------------- static device scratch (no allocations allowed) ----------------
__device__ float4   g_props[NA];
__device__ unsigned g_hist[NBINS + 1];      // [NBINS] = compact counter
__device__ int      g_B;
__device__ ull      g_k64in[NCAP], g_k64out[NCAP];
__device__ float4   g_box[TOPK];
__device__ float    g_bar[TOPK], g_bsc[TOPK];
__device__ ull      g_validm[96];
__device__ ull      g_mask[(size_t)TOPK * WORDS];
__device__ ulonglong2 g_re[(size_t)TOPK * WORDS];   // sparse row entries {bits, word}
__device__ int      g_rcnt[TOPK];

// anchor widths/heights: ratio {0.5:(23,12), 1:(16,16), 2:(11,22)} x scales {8,16,32}
__constant__ float c_aw[9] = {184.f,368.f,736.f,128.f,256.f,512.f, 88.f,176.f,352.f};
__constant__ float c_ah[9] = { 96.f,192.f,384.f,128.f,256.f,512.f,176.f,352.f,704.f};

// ---------------- 1) decode: thread = pixel, loop anchors (coalesced loads) ----------------
__global__ void decode_kernel(const float* __restrict__ dl, const float* __restrict__ sc)
{
    int pix = blockIdx.x * blockDim.x + threadIdx.x;   // 4096 pixels
    if (pix >= 4096) return;
    int w = pix & 63;
    int h = pix >> 6;
    float acx = (float)(16 * w + 8);
    float acy = (float)(16 * h + 8);

    for (int a = 0; a < 9; a++) {
        float s  = sc[(9 + a) * 4096 + pix];
        float d0 = dl[(a * 4 + 0) * 4096 + pix];
        float d1 = dl[(a * 4 + 1) * 4096 + pix];
        float d2 = dl[(a * 4 + 2) * 4096 + pix];
        float d3 = dl[(a * 4 + 3) * 4096 + pix];

        float aw = c_aw[a], ah = c_ah[a];

        // replicate reference fp32 op order exactly (no FMA contraction)
        float pcx = __fadd_rn(__fmul_rn(d0, aw), acx);
        float pcy = __fadd_rn(__fmul_rn(d1, ah), acy);
        float pw  = __fmul_rn(expf(d2), aw);
        float ph  = __fmul_rn(expf(d3), ah);
        float hw  = __fmul_rn(0.5f, pw);
        float hh  = __fmul_rn(0.5f, ph);

        float x1 = fminf(fmaxf(__fsub_rn(pcx, hw), 0.0f), 1023.0f);
        float y1 = fminf(fmaxf(__fsub_rn(pcy, hh), 0.0f), 1023.0f);
        float x2 = fminf(fmaxf(__fadd_rn(pcx, hw), 0.0f), 1023.0f);
        float y2 = fminf(fmaxf(__fadd_rn(pcy, hh), 0.0f), 1023.0f);

        int i = pix * 9 + a;
        g_props[i] = make_float4(x1, y1, x2, y2);

        bool keep = (__fadd_rn(__fsub_rn(x2, x1), 1.0f) >= 16.0f) &&
                    (__fadd_rn(__fsub_rn(y2, y1), 1.0f) >= 16.0f);
        if (keep) {
            int bin = min(NBINS - 1, (int)(s * (float)NBINS));   // s in [0,1)
            atomicAdd(&g_hist[bin], 1u);
        }
    }
}

// ---------------- 1b) threshold bin: largest B with suffix-count >= TOPK ----------------
__global__ void thresh_kernel()
{
    __shared__ unsigned sh[NBINS];
    __shared__ int sB;
    int t = threadIdx.x;
    sh[t] = g_hist[t];
    if (t == 0) sB = 0;
    __syncthreads();
    for (int off = 1; off < NBINS; off <<= 1) {
        unsigned v = sh[t] + ((t + off < NBINS) ? sh[t + off] : 0u);
        __syncthreads();
        sh[t] = v;
        __syncthreads();
    }
    if (sh[t] >= TOPK) atomicMax(&sB, t);
    __syncthreads();
    if (t == 0) g_B = sB;
}

// ---------------- 1c) compact candidates above threshold bin ----------------
__global__ void compact_kernel(const float* __restrict__ sc)
{
    int i = blockIdx.x * blockDim.x + threadIdx.x;
    if (i >= NA) return;
    // recompute keep + score (cheap; avoids storing 36K keys)
    float4 p = g_props[i];
    bool keep = (__fadd_rn(__fsub_rn(p.z, p.x), 1.0f) >= 16.0f) &&
                (__fadd_rn(__fsub_rn(p.w, p.y), 1.0f) >= 16.0f);
    if (!keep) return;
    int pix = i / 9;
    int a   = i - pix * 9;
    float s = sc[(9 + a) * 4096 + pix];
    int bin = min(NBINS - 1, (int)(s * (float)NBINS));
    if (bin < g_B) return;
    unsigned pos = atomicAdd(&g_hist[NBINS], 1u);
    if (pos < NCAP) {
        unsigned b   = __float_as_uint(s);
        unsigned ord = b | 0x80000000u;             // s >= 0 always here
        g_k64in[pos] = ((ull)ord << 16) | (unsigned)((~i) & 0xFFFF);  // NA < 65536
    }
}

// ---------------- 1d) O(N^2) exact rank + scatter ----------------
// rank[i] = #{j : key_j > key_i} + #{j < i : key_j == key_i}
// Padding item at pos p has key 0 -> rank = n + (p - n) = p (writes own slot).
__global__ void __launch_bounds__(512) rank_kernel()
{
    __shared__ int s_rank[32];
    int tid  = threadIdx.x;
    int item = blockIdx.x * 32 + (tid & 31);       // 32 items per block
    int q    = tid >> 5;                           // 16 key segments
    if (tid < 32) s_rank[tid] = 0;
    __syncthreads();

    ull ki = g_k64in[item];
    int j0 = q * (NCAP / 16);
    int r = 0;
    #pragma unroll 8
    for (int jj = 0; jj < NCAP / 16; jj++) {
        int j = j0 + jj;
        ull kj = __ldg(&g_k64in[j]);               // uniform address -> broadcast
        r += (kj > ki) || ((kj == ki) && (j < item));
    }
    atomicAdd(&s_rank[tid & 31], r);
    __syncthreads();
    if (tid < 32) g_k64out[s_rank[tid]] = ki;      // ranks form a permutation
}

// ---------------- 2) gather top-6000 into SoA + valid bitmask ----------------
__global__ void gather_kernel()
{
    int t = blockIdx.x * blockDim.x + threadIdx.x;   // 6144 threads
    float s; float4 p = make_float4(0.f, 0.f, 0.f, 0.f);
    if (t < TOPK) {
        ull k = g_k64out[t];
        unsigned idx = (~(unsigned)k) & 0xFFFFu;
        unsigned ord = (unsigned)(k >> 16);
        unsigned b   = (ord & 0x80000000u) ? (ord & 0x7FFFFFFFu) : ~ord;
        s = __uint_as_float(b);
        if (idx < NA) p = g_props[idx];
        else s = CUDART_NAN_F;                       // padding slot
    } else s = CUDART_NAN_F;
    bool v = isfinite(s);
    unsigned bal = __ballot_sync(0xFFFFFFFFu, v);
    if ((t & 31) == 0) ((unsigned*)g_validm)[t >> 5] = bal;
    if (t < TOPK) {
        g_box[t] = p; g_bsc[t] = s;
        g_bar[t] = __fmul_rn(__fadd_rn(__fsub_rn(p.z, p.x), 1.0f),
                             __fadd_rn(__fsub_rn(p.w, p.y), 1.0f));
    }
}

// ---------------- 3) suppression bitmask tiles (4 rows/thread, guarded fast-div) ----------------
__global__ void mask_kernel()
{
    int wd = blockIdx.x;
    int rowBase = blockIdx.y * 256;
    if (rowBase >= (wd + 1) * 64) return;           // tile fully below diagonal
    int tid = threadIdx.x;

    __shared__ float4 sc4[64];
    __shared__ float  scar[64];
    int j = wd * 64 + tid;
    if (j < TOPK) { sc4[tid] = g_box[j]; scar[tid] = g_bar[j]; }
    else { sc4[tid] = make_float4(3e9f, 3e9f, -3e9f, -3e9f); scar[tid] = 1.0f; }
    __syncthreads();

    float4 rb[4]; float rar[4]; ull acc[4], allowed[4]; int irow[4]; bool valid[4];
    #pragma unroll
    for (int r = 0; r < 4; r++) {
        int i = rowBase + r * 64 + tid;
        irow[r] = i;
        bool v = (i < TOPK);
        valid[r] = v;
        rb[r]  = v ? g_box[i] : make_float4(3e9f, 3e9f, -3e9f, -3e9f);
        rar[r] = v ? g_bar[i] : 1.0f;
        int sh = i - wd * 64 + 1;                   // keep bits kk >= sh (j > i)
        allowed[r] = (sh <= 0) ? ~0ULL : (sh >= 64 ? 0ULL : (~0ULL << sh));
        acc[r] = 0ULL;
    }

    #pragma unroll 4
    for (int kk = 0; kk < 64; kk++) {
        float4 c = sc4[kk]; float car = scar[kk];
        #pragma unroll
        for (int r = 0; r < 4; r++) {
            float iw = fmaxf(__fadd_rn(__fsub_rn(fminf(rb[r].z, c.z), fmaxf(rb[r].x, c.x)), 1.0f), 0.0f);
            float ih = fmaxf(__fadd_rn(__fsub_rn(fminf(rb[r].w, c.w), fmaxf(rb[r].y, c.y)), 1.0f), 0.0f);
            float inter = __fmul_rn(iw, ih);
            float un = __fsub_rn(__fadd_rn(rar[r], car), inter);
            float t = 0.7f * un;
            bool sup;
            if (inter > t * 1.0001f)       sup = true;    // surely > 0.7
            else if (inter <= t * 0.9999f) sup = false;   // surely <= 0.7
            else sup = (__fdiv_rn(inter, un) > 0.7f);     // rare exact path
            if (sup) acc[r] |= (1ULL << kk);
        }
    }
    #pragma unroll
    for (int r = 0; r < 4; r++)
        if (valid[r]) g_mask[(size_t)irow[r] * WORDS + wd] = acc[r] & allowed[r];
}

// ---------------- 3b) compress rows to sparse entries (own word + 2 onward) ----------------
__global__ void compress_kernel()
{
    int gi = blockIdx.x * blockDim.x + threadIdx.x;
    int i = gi >> 5, lane = gi & 31;
    if (i >= TOPK) return;
    int wlo = (i >> 6) + 2;
    int cnt = 0;
    for (int base = wlo; base < WORDS; base += 32) {
        int wd = base + lane;
        ull m = (wd < WORDS) ? g_mask[(size_t)i * WORDS + wd] : 0ULL;
        unsigned bal = __ballot_sync(0xFFFFFFFFu, m != 0ULL);
        if (m) g_re[(size_t)i * WORDS + cnt + __popc(bal & ((1u << lane) - 1u))] =
                   make_ulonglong2(m, (ull)wd);
        cnt += __popc(bal);
    }
    if (!lane) g_rcnt[i] = cnt;
}

// ---------------- 4) pipelined greedy scan: batched-MLP deferred suppression ----------------
__global__ void __launch_bounds__(256) scan_kernel(float* __restrict__ out)
{
    __shared__ ull removed[WPAD];
    __shared__ ull sval[WPAD];
    __shared__ ull sdiag[2][64];
    __shared__ ull snext[2][64];
    __shared__ unsigned s_rownz[2][2];
    __shared__ int s_slist[POST];
    __shared__ unsigned char s_rcnt[TOPK];
    __shared__ int s_count, s_c0;
    int tid = threadIdx.x, wid = tid >> 5, lane = tid & 31;

    for (int t = tid; t < TOPK; t += 256) s_rcnt[t] = (unsigned char)g_rcnt[t];
    if (tid < WPAD) { removed[tid] = 0ULL; sval[tid] = (tid < WORDS) ? g_validm[tid] : 0ULL; }
    if (!tid) { s_count = 0; s_c0 = 0; }
    if (wid >= 6) {                                  // prefetch word 0 diag + nextcol
        int t = tid - 192;
        ull dm = g_mask[(size_t)t * WORDS + 0];
        sdiag[0][t] = dm;
        snext[0][t] = g_mask[(size_t)t * WORDS + 1];
        unsigned bal = __ballot_sync(0xFFFFFFFFu, dm != 0ULL);
        if (!lane) s_rownz[0][wid - 6] = bal;
    }
    __syncthreads();

    int count = 0, klo = 0, khi = 0;
    for (int w = 0; w < WORDS; w++) {
        int buf = w & 1;
        if (!tid) {
            // Phase B: greedy chain; clear-lowest-bit keeps the dependency short
            ull alive = sval[w] & ~removed[w];
            ull rn = ((ull)s_rownz[buf][1] << 32) | s_rownz[buf][0];
            const ull* diag = sdiag[buf];
            const ull* nxt  = snext[buf];
            ull urg = 0ULL;
            int c = s_count; s_c0 = c;
            while (alive && c < POST) {
                ull next_alive = alive & (alive - 1);   // clear lowest set bit
                ull bit = alive & ~next_alive;          // the kept bit
                int b = __ffsll(alive) - 1;             // off-chain
                s_slist[c++] = w * 64 + b;
                urg |= nxt[b];
                if (rn & bit) next_alive &= ~diag[b];
                alive = next_alive;
            }
            s_count = c;
            if (urg && w + 1 < WORDS) atomicOr(&removed[w + 1], urg);
        } else if (wid >= 6) {
            // prefetch diag + nextcol for word w+1
            if (w + 1 < WORDS) {
                int t = tid - 192;
                int row = (w + 1) * 64 + t;
                ull dm = 0ULL, nm = 0ULL;
                if (row < TOPK) {
                    dm = g_mask[(size_t)row * WORDS + (w + 1)];
                    if (w + 2 < WORDS) nm = g_mask[(size_t)row * WORDS + (w + 2)];
                }
                sdiag[buf ^ 1][t] = dm;
                snext[buf ^ 1][t] = nm;
                unsigned bal = __ballot_sync(0xFFFFFFFFu, dm != 0ULL);
                if (!lane) s_rownz[buf ^ 1][wid - 6] = bal;
            }
        } else if (tid >= 32) {
            // deferred K_{w-1}: 160 threads, 4 lanes/box (40 slots), 4-deep batched loads
            int t = tid - 32;
            int nk = khi - klo;
            for (int slot = t >> 2; slot < nk; slot += 40) {
                int idx = s_slist[klo + slot];
                int cnt = s_rcnt[idx];
                const ulonglong2* re = &g_re[(size_t)idx * WORDS];
                for (int e = (t & 3); e < cnt; e += 16) {
                    ulonglong2 e0 = re[e];
                    ulonglong2 e1, e2, e3;
                    bool b1 = (e + 4) < cnt, b2 = (e + 8) < cnt, b3 = (e + 12) < cnt;
                    if (b1) e1 = re[e + 4];
                    if (b2) e2 = re[e + 8];
                    if (b3) e3 = re[e + 12];
                    atomicOr(&removed[(int)e0.y], e0.x);
                    if (b1) atomicOr(&removed[(int)e1.y], e1.x);
                    if (b2) atomicOr(&removed[(int)e2.y], e2.x);
                    if (b3) atomicOr(&removed[(int)e3.y], e3.x);
                }
            }
        }
        __syncthreads();
        klo = s_c0; khi = s_count; count = s_count;
        if (count >= POST) break;
    }

    // output
    int total = min(count, POST);
    float* outs = out + POST * 5;
    for (int t = tid; t < total; t += 256) {
        int i = s_slist[t];
        float4 p = g_box[i];
        out[t * 5 + 1] = p.x; out[t * 5 + 2] = p.y;
        out[t * 5 + 3] = p.z; out[t * 5 + 4] = p.w;
        outs[t] = g_bsc[i];
    }
}

// ---------------- launch ----------------
extern "C" void kernel_launch(void* const* d_in, const int* in_sizes, int n_in,
                              void* d_out, int out_size)
{
    const float* deltas = (const float*)d_in[0];
    const float* scores = (const float*)d_in[1];

    cudaMemsetAsync(d_out, 0, (size_t)out_size * sizeof(float), 0);
    void* p;
    cudaGetSymbolAddress(&p, g_hist);  cudaMemsetAsync(p, 0, sizeof(g_hist), 0);
    cudaGetSymbolAddress(&p, g_k64in); cudaMemsetAsync(p, 0, sizeof(g_k64in), 0);

    decode_kernel<<<16, 256>>>(deltas, scores);          // 4096 pixel threads
    thresh_kernel<<<1, NBINS>>>();
    compact_kernel<<<NA / 256, 256>>>(scores);
    rank_kernel<<<NCAP / 32, 512>>>();                   // 192 blocks, 512 threads
    gather_kernel<<<24, 256>>>();                        // 6144 threads

    mask_kernel<<<dim3(WORDS, (TOPK + 255) / 256), 64>>>();
    compress_kernel<<<TOPK * 32 / 256, 256>>>();
    scan_kernel<<<1, 256>>>((float*)d_out);
}

// round 15
// speedup vs baseline: 1.9245x; 1.0289x over previous
#include <cuda_runtime.h>
#include <math_constants.h>
#include <cstdint>

#define NA    36864      // 64*64*9 proposals
#define TOPK  6000
#define POST  2000
#define WORDS 94         // ceil(6000/64)
#define WPAD  96
#define NCAP  6144       // compacted capacity (suffix(B) < 6000 + count(B) << 6144)
#define NBINS 1024

typedef unsigned long long ull;

// ---------------- static device scratch (no allocations allowed) ----------------
// NOTE: __device__ globals are zero-initialized at module load; scan_kernel
// re-zeroes g_hist at its end so every graph replay starts from the same state.
__device__ float4   g_props[NA];
__device__ unsigned g_hist[NBINS + 1];      // [NBINS] = compact counter
__device__ int      g_B;
__device__ ull      g_k64in[NCAP], g_k64out[NCAP];
__device__ float4   g_box[TOPK];
__device__ float    g_bar[TOPK], g_bsc[TOPK];
__device__ ull      g_validm[96];
__device__ ull      g_mask[(size_t)TOPK * WORDS];
__device__ ulonglong2 g_re[(size_t)TOPK * WORDS];   // sparse row entries {bits, word}
__device__ int      g_rcnt[TOPK];

// anchor widths/heights: ratio {0.5:(23,12), 1:(16,16), 2:(11,22)} x scales {8,16,32}
__constant__ float c_aw[9] = {184.f,368.f,736.f,128.f,256.f,512.f, 88.f,176.f,352.f};
__constant__ float c_ah[9] = { 96.f,192.f,384.f,128.f,256.f,512.f,176.f,352.f,704.f};

// ---------------- 1) decode: thread = pixel, loop anchors (coalesced loads) ----------------
__global__ void decode_kernel(const float* __restrict__ dl, const float* __restrict__ sc)
{
    int pix = blockIdx.x * blockDim.x + threadIdx.x;   // 4096 pixels
    if (pix >= 4096) return;
    int w = pix & 63;
    int h = pix >> 6;
    float acx = (float)(16 * w + 8);
    float acy = (float)(16 * h + 8);

    for (int a = 0; a < 9; a++) {
        float s  = sc[(9 + a) * 4096 + pix];
        float d0 = dl[(a * 4 + 0) * 4096 + pix];
        float d1 = dl[(a * 4 + 1) * 4096 + pix];
        float d2 = dl[(a * 4 + 2) * 4096 + pix];
        float d3 = dl[(a * 4 + 3) * 4096 + pix];

        float aw = c_aw[a], ah = c_ah[a];

        // replicate reference fp32 op order exactly (no FMA contraction)
        float pcx = __fadd_rn(__fmul_rn(d0, aw), acx);
        float pcy = __fadd_rn(__fmul_rn(d1, ah), acy);
        float pw  = __fmul_rn(expf(d2), aw);
        float ph  = __fmul_rn(expf(d3), ah);
        float hw  = __fmul_rn(0.5f, pw);
        float hh  = __fmul_rn(0.5f, ph);

        float x1 = fminf(fmaxf(__fsub_rn(pcx, hw), 0.0f), 1023.0f);
        float y1 = fminf(fmaxf(__fsub_rn(pcy, hh), 0.0f), 1023.0f);
        float x2 = fminf(fmaxf(__fadd_rn(pcx, hw), 0.0f), 1023.0f);
        float y2 = fminf(fmaxf(__fadd_rn(pcy, hh), 0.0f), 1023.0f);

        int i = pix * 9 + a;
        g_props[i] = make_float4(x1, y1, x2, y2);

        bool keep = (__fadd_rn(__fsub_rn(x2, x1), 1.0f) >= 16.0f) &&
                    (__fadd_rn(__fsub_rn(y2, y1), 1.0f) >= 16.0f);
        if (keep) {
            int bin = min(NBINS - 1, (int)(s * (float)NBINS));   // s in [0,1)
            atomicAdd(&g_hist[bin], 1u);
        }
    }
}

// ---------------- 1b) threshold bin: largest B with suffix-count >= TOPK ----------------
__global__ void thresh_kernel()
{
    __shared__ unsigned sh[NBINS];
    __shared__ int sB;
    int t = threadIdx.x;
    sh[t] = g_hist[t];
    if (t == 0) sB = 0;
    __syncthreads();
    for (int off = 1; off < NBINS; off <<= 1) {
        unsigned v = sh[t] + ((t + off < NBINS) ? sh[t + off] : 0u);
        __syncthreads();
        sh[t] = v;
        __syncthreads();
    }
    if (sh[t] >= TOPK) atomicMax(&sB, t);
    __syncthreads();
    if (t == 0) g_B = sB;
}

// ---------------- 1c) compact candidates above threshold bin ----------------
__global__ void compact_kernel(const float* __restrict__ sc)
{
    int i = blockIdx.x * blockDim.x + threadIdx.x;
    if (i >= NA) return;
    float4 p = g_props[i];
    bool keep = (__fadd_rn(__fsub_rn(p.z, p.x), 1.0f) >= 16.0f) &&
                (__fadd_rn(__fsub_rn(p.w, p.y), 1.0f) >= 16.0f);
    if (!keep) return;
    int pix = i / 9;
    int a   = i - pix * 9;
    float s = sc[(9 + a) * 4096 + pix];
    int bin = min(NBINS - 1, (int)(s * (float)NBINS));
    if (bin < g_B) return;
    unsigned pos = atomicAdd(&g_hist[NBINS], 1u);
    if (pos < NCAP) {
        unsigned b   = __float_as_uint(s);
        unsigned ord = b | 0x80000000u;             // s >= 0 always here
        g_k64in[pos] = ((ull)ord << 16) | (unsigned)((~i) & 0xFFFF);  // NA < 65536
    }
}

// ---------------- 1d) O(N^2) exact rank + scatter (1024 threads, 32 segments) ----------------
// rank[i] = #{j : key_j > key_i} + #{j < i : key_j == key_i}
// Padding item at pos p has key 0 -> rank = n + (p - n) = p (writes own slot).
__global__ void __launch_bounds__(1024) rank_kernel()
{
    __shared__ int s_rank[32];
    int tid  = threadIdx.x;
    int item = blockIdx.x * 32 + (tid & 31);       // 32 items per block
    int q    = tid >> 5;                           // 32 key segments of 192
    if (tid < 32) s_rank[tid] = 0;
    __syncthreads();

    ull ki = g_k64in[item];
    int j0 = q * (NCAP / 32);
    int r = 0;
    #pragma unroll 8
    for (int jj = 0; jj < NCAP / 32; jj++) {
        int j = j0 + jj;
        ull kj = __ldg(&g_k64in[j]);               // uniform address -> broadcast
        r += (kj > ki) || ((kj == ki) && (j < item));
    }
    atomicAdd(&s_rank[tid & 31], r);
    __syncthreads();
    if (tid < 32) g_k64out[s_rank[tid]] = ki;      // ranks form a permutation
}

// ---------------- 2) gather top-6000 into SoA + valid bitmask ----------------
__global__ void gather_kernel()
{
    int t = blockIdx.x * blockDim.x + threadIdx.x;   // 6144 threads
    float s; float4 p = make_float4(0.f, 0.f, 0.f, 0.f);
    if (t < TOPK) {
        ull k = g_k64out[t];
        unsigned idx = (~(unsigned)k) & 0xFFFFu;
        unsigned ord = (unsigned)(k >> 16);
        unsigned b   = (ord & 0x80000000u) ? (ord & 0x7FFFFFFFu) : ~ord;
        s = __uint_as_float(b);
        if (idx < NA) p = g_props[idx];
        else s = CUDART_NAN_F;                       // padding slot
    } else s = CUDART_NAN_F;
    bool v = isfinite(s);
    unsigned bal = __ballot_sync(0xFFFFFFFFu, v);
    if ((t & 31) == 0) ((unsigned*)g_validm)[t >> 5] = bal;
    if (t < TOPK) {
        g_box[t] = p; g_bsc[t] = s;
        g_bar[t] = __fmul_rn(__fadd_rn(__fsub_rn(p.z, p.x), 1.0f),
                             __fadd_rn(__fsub_rn(p.w, p.y), 1.0f));
    }
}

// ---------------- 3) suppression bitmask tiles (4 rows/thread, guarded fast-div) ----------------
__global__ void mask_kernel()
{
    int wd = blockIdx.x;
    int rowBase = blockIdx.y * 256;
    if (rowBase >= (wd + 1) * 64) return;           // tile fully below diagonal
    int tid = threadIdx.x;

    __shared__ float4 sc4[64];
    __shared__ float  scar[64];
    int j = wd * 64 + tid;
    if (j < TOPK) { sc4[tid] = g_box[j]; scar[tid] = g_bar[j]; }
    else { sc4[tid] = make_float4(3e9f, 3e9f, -3e9f, -3e9f); scar[tid] = 1.0f; }
    __syncthreads();

    float4 rb[4]; float rar[4]; ull acc[4], allowed[4]; int irow[4]; bool valid[4];
    #pragma unroll
    for (int r = 0; r < 4; r++) {
        int i = rowBase + r * 64 + tid;
        irow[r] = i;
        bool v = (i < TOPK);
        valid[r] = v;
        rb[r]  = v ? g_box[i] : make_float4(3e9f, 3e9f, -3e9f, -3e9f);
        rar[r] = v ? g_bar[i] : 1.0f;
        int sh = i - wd * 64 + 1;                   // keep bits kk >= sh (j > i)
        allowed[r] = (sh <= 0) ? ~0ULL : (sh >= 64 ? 0ULL : (~0ULL << sh));
        acc[r] = 0ULL;
    }

    #pragma unroll 4
    for (int kk = 0; kk < 64; kk++) {
        float4 c = sc4[kk]; float car = scar[kk];
        #pragma unroll
        for (int r = 0; r < 4; r++) {
            float iw = fmaxf(__fadd_rn(__fsub_rn(fminf(rb[r].z, c.z), fmaxf(rb[r].x, c.x)), 1.0f), 0.0f);
            float ih = fmaxf(__fadd_rn(__fsub_rn(fminf(rb[r].w, c.w), fmaxf(rb[r].y, c.y)), 1.0f), 0.0f);
            float inter = __fmul_rn(iw, ih);
            float un = __fsub_rn(__fadd_rn(rar[r], car), inter);
            float t = 0.7f * un;
            bool sup;
            if (inter > t * 1.0001f)       sup = true;    // surely > 0.7
            else if (inter <= t * 0.9999f) sup = false;   // surely <= 0.7
            else sup = (__fdiv_rn(inter, un) > 0.7f);     // rare exact path
            if (sup) acc[r] |= (1ULL << kk);
        }
    }
    #pragma unroll
    for (int r = 0; r < 4; r++)
        if (valid[r]) g_mask[(size_t)irow[r] * WORDS + wd] = acc[r] & allowed[r];
}

// ---------------- 3b) compress rows to sparse entries (own word + 2 onward) ----------------
__global__ void compress_kernel()
{
    int gi = blockIdx.x * blockDim.x + threadIdx.x;
    int i = gi >> 5, lane = gi & 31;
    if (i >= TOPK) return;
    int wlo = (i >> 6) + 2;
    int cnt = 0;
    for (int base = wlo; base < WORDS; base += 32) {
        int wd = base + lane;
        ull m = (wd < WORDS) ? g_mask[(size_t)i * WORDS + wd] : 0ULL;
        unsigned bal = __ballot_sync(0xFFFFFFFFu, m != 0ULL);
        if (m) g_re[(size_t)i * WORDS + cnt + __popc(bal & ((1u << lane) - 1u))] =
                   make_ulonglong2(m, (ull)wd);
        cnt += __popc(bal);
    }
    if (!lane) g_rcnt[i] = cnt;
}

// ---------------- 4) pipelined greedy scan + full output write + scratch re-zero ----------------
__global__ void __launch_bounds__(256) scan_kernel(float* __restrict__ out)
{
    __shared__ ull removed[WPAD];
    __shared__ ull sval[WPAD];
    __shared__ ull sdiag[2][64];
    __shared__ ull snext[2][64];
    __shared__ unsigned s_rownz[2][2];
    __shared__ int s_slist[POST];
    __shared__ unsigned char s_rcnt[TOPK];
    __shared__ int s_count, s_c0;
    int tid = threadIdx.x, wid = tid >> 5, lane = tid & 31;

    for (int t = tid; t < TOPK; t += 256) s_rcnt[t] = (unsigned char)g_rcnt[t];
    if (tid < WPAD) { removed[tid] = 0ULL; sval[tid] = (tid < WORDS) ? g_validm[tid] : 0ULL; }
    if (!tid) { s_count = 0; s_c0 = 0; }
    if (wid >= 6) {                                  // prefetch word 0 diag + nextcol
        int t = tid - 192;
        ull dm = g_mask[(size_t)t * WORDS + 0];
        sdiag[0][t] = dm;
        snext[0][t] = g_mask[(size_t)t * WORDS + 1];
        unsigned bal = __ballot_sync(0xFFFFFFFFu, dm != 0ULL);
        if (!lane) s_rownz[0][wid - 6] = bal;
    }
    __syncthreads();

    int count = 0, klo = 0, khi = 0;
    for (int w = 0; w < WORDS; w++) {
        int buf = w & 1;
        bool done = (khi >= POST);                   // Phase B may have finished last word
        if (!tid) {
            // Phase B: greedy chain; clear-lowest-bit keeps the dependency short
            ull alive = sval[w] & ~removed[w];
            ull rn = ((ull)s_rownz[buf][1] << 32) | s_rownz[buf][0];
            const ull* diag = sdiag[buf];
            const ull* nxt  = snext[buf];
            ull urg = 0ULL;
            int c = s_count; s_c0 = c;
            while (alive && c < POST) {
                ull next_alive = alive & (alive - 1);   // clear lowest set bit
                ull bit = alive & ~next_alive;          // the kept bit
                int b = __ffsll(alive) - 1;             // off-chain
                s_slist[c++] = w * 64 + b;
                urg |= nxt[b];
                if (rn & bit) next_alive &= ~diag[b];
                alive = next_alive;
            }
            s_count = c;
            if (urg && w + 1 < WORDS) atomicOr(&removed[w + 1], urg);
        } else if (wid >= 6) {
            // prefetch diag + nextcol for word w+1
            if (w + 1 < WORDS && !done) {
                int t = tid - 192;
                int row = (w + 1) * 64 + t;
                ull dm = 0ULL, nm = 0ULL;
                if (row < TOPK) {
                    dm = g_mask[(size_t)row * WORDS + (w + 1)];
                    if (w + 2 < WORDS) nm = g_mask[(size_t)row * WORDS + (w + 2)];
                }
                sdiag[buf ^ 1][t] = dm;
                snext[buf ^ 1][t] = nm;
                unsigned bal = __ballot_sync(0xFFFFFFFFu, dm != 0ULL);
                if (!lane) s_rownz[buf ^ 1][wid - 6] = bal;
            }
        } else if (tid >= 32 && !done) {
            // deferred K_{w-1}: 160 threads, 4 lanes/box (40 slots), 4-deep batched loads
            int t = tid - 32;
            int nk = khi - klo;
            for (int slot = t >> 2; slot < nk; slot += 40) {
                int idx = s_slist[klo + slot];
                int cnt = s_rcnt[idx];
                const ulonglong2* re = &g_re[(size_t)idx * WORDS];
                for (int e = (t & 3); e < cnt; e += 16) {
                    ulonglong2 e0 = re[e];
                    ulonglong2 e1, e2, e3;
                    bool b1 = (e + 4) < cnt, b2 = (e + 8) < cnt, b3 = (e + 12) < cnt;
                    if (b1) e1 = re[e + 4];
                    if (b2) e2 = re[e + 8];
                    if (b3) e3 = re[e + 12];
                    atomicOr(&removed[(int)e0.y], e0.x);
                    if (b1) atomicOr(&removed[(int)e1.y], e1.x);
                    if (b2) atomicOr(&removed[(int)e2.y], e2.x);
                    if (b3) atomicOr(&removed[(int)e3.y], e3.x);
                }
            }
        }
        __syncthreads();
        klo = s_c0; khi = s_count; count = s_count;
        if (count >= POST) break;
    }

    // output: write ALL 2000 rows (values or zeros) -- no host memset needed
    int total = min(count, POST);
    float* outs = out + POST * 5;
    for (int t = tid; t < POST; t += 256) {
        if (t < total) {
            int i = s_slist[t];
            float4 p = g_box[i];
            out[t * 5 + 0] = 0.0f;
            out[t * 5 + 1] = p.x; out[t * 5 + 2] = p.y;
            out[t * 5 + 3] = p.z; out[t * 5 + 4] = p.w;
            outs[t] = g_bsc[i];
        } else {
            out[t * 5 + 0] = 0.0f; out[t * 5 + 1] = 0.0f; out[t * 5 + 2] = 0.0f;
            out[t * 5 + 3] = 0.0f; out[t * 5 + 4] = 0.0f;
            outs[t] = 0.0f;
        }
    }

    // re-zero scratch for the next graph replay (g_k64in slots >= n are never dirtied)
    for (int t = tid; t <= NBINS; t += 256) g_hist[t] = 0u;
}

// ---------------- launch ----------------
extern "C" void kernel_launch(void* const* d_in, const int* in_sizes, int n_in,
                              void* d_out, int out_size)
{
    const float* deltas = (const float*)d_in[0];
    const float* scores = (const float*)d_in[1];

    decode_kernel<<<16, 256>>>(deltas, scores);          // 4096 pixel threads
    thresh_kernel<<<1, NBINS>>>();
    compact_kernel<<<NA / 256, 256>>>(scores);
    rank_kernel<<<NCAP / 32, 1024>>>();                  // 192 blocks, 1024 threads
    gather_kernel<<<24, 256>>>();                        // 6144 threads

    mask_kernel<<<dim3(WORDS, (TOPK + 255) / 256), 64>>>();
    compress_kernel<<<TOPK * 32 / 256, 256>>>();
    scan_kernel<<<1, 256>>>((float*)d_out);
}